// round 7
// baseline (speedup 1.0000x reference)
#include <cuda_runtime.h>
#include <math.h>
#include <stdint.h>

// ---------------------------------------------------------------------------
// SpecDecoder: 127-step LSTM + fused 3-layer MLP, all GEMMs mma.sync tf32.
// Frag-major storage everywhere; MMA dependency chains broken; MLP transposed
// (W is the m-operand) so every m16 tile is full. One grid sync per step.
// ---------------------------------------------------------------------------

#define BATCH 1024
#define HID   512
#define EMB   256
#define SEQL  128
#define STEPS (SEQL - 1)
#define NBLK  128
#define NTHR  256
#define NCHUNK 24              // BK=32 chunks over KGATE=768
#define DSMEM 122880           // gates 3*32KB + sH 16KB + sZ1 4KB + sZ2 4KB

// ---------------- device scratch (frag-major) -------------------------------
__device__ float4 g_xf4[8388608];      // [t][kc 0..15][m8 0..127][lane]
__device__ float4 g_hf4[2][131072];    // [kc 0..31][m8 0..127][lane]
__device__ float4 g_Wf4[393216];       // gates W: [kc 0..47][n8' 0..255][lane]
__device__ float4 g_W1A[16384];        // W1 A-frags: [m16 0..7][kc 0..31][lane][2]
__device__ float4 g_W2A[4096];         // W2 A-frags: [m16 0..7][kc 0..7][lane][2]
__device__ float4 g_W3A[8192];         // W3 A-frags: [m16 0..15][kc 0..7][lane][2]
__device__ float  g_bc[2048];          // combined LSTM bias, original order
__device__ float  g_c[BATCH * HID];    // cell state, row-major
__device__ unsigned g_bar;

// ---------------------------------------------------------------------------
__device__ __forceinline__ float tfr(float x) {
    uint32_t r;
    asm("cvt.rna.tf32.f32 %0, %1;" : "=r"(r) : "f"(x));
    return __uint_as_float(r);
}

__device__ __forceinline__ void mma_tf32(float* c,
                                         float a0, float a1, float a2, float a3,
                                         float b0, float b1) {
    asm volatile(
        "mma.sync.aligned.m16n8k8.row.col.f32.tf32.tf32.f32 "
        "{%0,%1,%2,%3}, {%4,%5,%6,%7}, {%8,%9}, {%0,%1,%2,%3};"
        : "+f"(c[0]), "+f"(c[1]), "+f"(c[2]), "+f"(c[3])
        : "r"(__float_as_uint(a0)), "r"(__float_as_uint(a1)),
          "r"(__float_as_uint(a2)), "r"(__float_as_uint(a3)),
          "r"(__float_as_uint(b0)), "r"(__float_as_uint(b1)));
}

#define CP_ASYNC16(dst, src) \
    asm volatile("cp.async.ca.shared.global [%0], [%1], 16;\n" :: "r"(dst), "l"(src))
#define CP_COMMIT() asm volatile("cp.async.commit_group;\n" ::: "memory")

__device__ __forceinline__ float fast_sig(float x) {
    return __fdividef(1.f, 1.f + __expf(-x));
}
__device__ __forceinline__ float fast_tanh(float x) {
    return 1.f - __fdividef(2.f, __expf(2.f * x) + 1.f);
}

__device__ __forceinline__ void grid_sync() {
    __syncthreads();
    if (threadIdx.x == 0) {
        __threadfence();
        unsigned old = atomicAdd(&g_bar, 1u);
        unsigned target = (old / NBLK + 1u) * NBLK;
        while (*((volatile unsigned*)&g_bar) < target) { }
        __threadfence();
    }
    __syncthreads();
}

// ---------------------------------------------------------------------------
// Init. Gate permutation: n' = b8*32 + g*8 + u <-> n = g*HID + b8*8 + u.
// ---------------------------------------------------------------------------
__global__ void init_kernel(const float* __restrict__ hidden,
                            const float* __restrict__ pts,
                            const float* __restrict__ W_ih,
                            const float* __restrict__ W_hh,
                            const float* __restrict__ b_ih,
                            const float* __restrict__ b_hh,
                            const float* __restrict__ W1,
                            const float* __restrict__ W2,
                            const float* __restrict__ W3,
                            float* __restrict__ out) {
    const int idx0 = blockIdx.x * blockDim.x + threadIdx.x;
    const int stride = gridDim.x * blockDim.x;
    if (idx0 == 0) g_bar = 0u;

    // x frag-major (B/A dual-use layout)
    for (int q = idx0; q < 8388608; q += stride) {
        int lane = q & 31, m8 = (q >> 5) & 127, kc = (q >> 12) & 15, t = q >> 16;
        int gid = lane >> 2, tig = lane & 3;
        const float* p = pts + (size_t)(m8 * 8 + gid) * (SEQL * EMB)
                             + (size_t)t * EMB + kc * 16 + tig;
        g_xf4[q] = make_float4(tfr(p[0]), tfr(p[4]), tfr(p[8]), tfr(p[12]));
    }
    // h0 frag-major
    for (int q = idx0; q < 131072; q += stride) {
        int lane = q & 31, m8 = (q >> 5) & 127, kc = q >> 12;
        int gid = lane >> 2, tig = lane & 3;
        const float* p = hidden + (size_t)(m8 * 8 + gid) * HID + kc * 16 + tig;
        g_hf4[0][q] = make_float4(tfr(p[0]), tfr(p[4]), tfr(p[8]), tfr(p[12]));
    }
    // gates W frag-major (B-frags, permuted)
    for (int q = idx0; q < 393216; q += stride) {
        int lane = q & 31, n8 = (q >> 5) & 255, kc = q >> 13;
        int gid = lane >> 2, tig = lane & 3;
        int b8 = n8 >> 2, g = n8 & 3;
        int n = g * HID + b8 * 8 + gid;
        int k = kc * 16 + tig;
        float v[4];
#pragma unroll
        for (int s = 0; s < 4; s++) {
            int kk = k + 4 * s;
            v[s] = (kk < EMB) ? W_ih[(size_t)n * EMB + kk]
                              : W_hh[(size_t)n * HID + (kk - EMB)];
        }
        g_Wf4[q] = make_float4(tfr(v[0]), tfr(v[1]), tfr(v[2]), tfr(v[3]));
    }
    // MLP weights as A-fragments: [(m16*KC + kc)*32 + lane]*2 + p
    for (int q = idx0; q < 16384; q += stride) {
        int p2 = q & 1, lane = (q >> 1) & 31, kc = (q >> 6) & 31, m16 = q >> 11;
        int gid = lane >> 2, tig = lane & 3;
        int r0 = m16 * 16 + gid, kb = kc * 16 + p2 * 8;
        g_W1A[q] = make_float4(tfr(W1[(size_t)r0 * HID + kb + tig]),
                               tfr(W1[(size_t)(r0 + 8) * HID + kb + tig]),
                               tfr(W1[(size_t)r0 * HID + kb + tig + 4]),
                               tfr(W1[(size_t)(r0 + 8) * HID + kb + tig + 4]));
    }
    for (int q = idx0; q < 4096; q += stride) {
        int p2 = q & 1, lane = (q >> 1) & 31, kc = (q >> 6) & 7, m16 = q >> 9;
        int gid = lane >> 2, tig = lane & 3;
        int r0 = m16 * 16 + gid, kb = kc * 16 + p2 * 8;
        g_W2A[q] = make_float4(tfr(W2[(size_t)r0 * 128 + kb + tig]),
                               tfr(W2[(size_t)(r0 + 8) * 128 + kb + tig]),
                               tfr(W2[(size_t)r0 * 128 + kb + tig + 4]),
                               tfr(W2[(size_t)(r0 + 8) * 128 + kb + tig + 4]));
    }
    for (int q = idx0; q < 8192; q += stride) {
        int p2 = q & 1, lane = (q >> 1) & 31, kc = (q >> 6) & 7, m16 = q >> 9;
        int gid = lane >> 2, tig = lane & 3;
        int r0 = m16 * 16 + gid, kb = kc * 16 + p2 * 8;
        g_W3A[q] = make_float4(tfr(W3[(size_t)r0 * 128 + kb + tig]),
                               tfr(W3[(size_t)(r0 + 8) * 128 + kb + tig]),
                               tfr(W3[(size_t)r0 * 128 + kb + tig + 4]),
                               tfr(W3[(size_t)(r0 + 8) * 128 + kb + tig + 4]));
    }
    for (int i = idx0; i < BATCH * HID; i += stride) g_c[i] = 0.f;
    for (int i = idx0; i < 2048; i += stride) g_bc[i] = b_ih[i] + b_hh[i];
    for (int i = idx0; i < BATCH * EMB; i += stride) {
        int b = i / EMB, e = i % EMB;
        out[(size_t)b * (SEQL * EMB) + e] = (e == 0) ? 1.f : 0.f;
    }
}

// ---------------------------------------------------------------------------
// Gates prefetch: one BK=32 chunk (A 16KB + B 16KB) into stage ci%3.
// ---------------------------------------------------------------------------
__device__ __forceinline__ void gates_pf(float* dsm, int ci, int t,
                                         int m8b, int n8b, const float4* hf) {
    const int tid = threadIdx.x;
    float* stage = dsm + (ci % 3) * 8192;
#pragma unroll
    for (int j = 0; j < 8; j++) {
        int u = j * 256 + tid;
        unsigned dst = (unsigned)__cvta_generic_to_shared(stage + u * 4);
        const float4* src;
        if (u < 1024) {
            int kc2 = u >> 9, r = u & 511, grp = r >> 5, ln = r & 31;
            int kc = ci * 2 + kc2;
            src = (kc < 16)
                ? (g_xf4 + (((size_t)(t * 16 + kc) * 128 + m8b + grp) << 5) + ln)
                : (hf + (((size_t)(kc - 16) * 128 + m8b + grp) << 5) + ln);
        } else {
            int u2 = u - 1024;
            int kc2 = u2 >> 9, r = u2 & 511, grp = r >> 5, ln = r & 31;
            src = g_Wf4 + (((size_t)(ci * 2 + kc2) * 256 + n8b + grp) << 5) + ln;
        }
        CP_ASYNC16(dst, src);
    }
    CP_COMMIT();
}

// ---------------------------------------------------------------------------
// Gates: 128x128 CTA tile, 8 warps (2x4), warp tile 64x32, fused LSTM epi.
// MMA order: all 16 (mt,nt) for k8-lo, then all 16 for k8-hi (dep gap = 16).
// ---------------------------------------------------------------------------
__device__ void phase_gates(int t, int cur, float* dsm) {
    const int tile = blockIdx.x;
    const int m8b = (tile >> 4) * 16, n8b = (tile & 15) * 16;
    const int tid = threadIdx.x, lane = tid & 31, wid = tid >> 5;
    const int wr = wid >> 2, wc = wid & 3;
    const int gid = lane >> 2, tig = lane & 3;
    const float4* hf = g_hf4[cur];

    float acc[4][4][4];
#pragma unroll
    for (int mt = 0; mt < 4; mt++)
#pragma unroll
        for (int nt = 0; nt < 4; nt++)
#pragma unroll
            for (int r = 0; r < 4; r++) acc[mt][nt][r] = 0.f;

    gates_pf(dsm, 0, t, m8b, n8b, hf);
    gates_pf(dsm, 1, t, m8b, n8b, hf);

#pragma unroll 1
    for (int ci = 0; ci < NCHUNK; ci++) {
        if (ci + 2 < NCHUNK) {
            gates_pf(dsm, ci + 2, t, m8b, n8b, hf);
            asm volatile("cp.async.wait_group 2;\n" ::: "memory");
        } else if (ci + 1 < NCHUNK) {
            asm volatile("cp.async.wait_group 1;\n" ::: "memory");
        } else {
            asm volatile("cp.async.wait_group 0;\n" ::: "memory");
        }
        __syncthreads();

        const float4* sA4 = (const float4*)(dsm + (ci % 3) * 8192);
        const float4* sB4 = sA4 + 1024;
#pragma unroll
        for (int kc2 = 0; kc2 < 2; kc2++) {
            float4 af[8];
#pragma unroll
            for (int g8 = 0; g8 < 8; g8++)
                af[g8] = sA4[kc2 * 512 + (wr * 8 + g8) * 32 + lane];
            float4 bf[4];
#pragma unroll
            for (int nb = 0; nb < 4; nb++)
                bf[nb] = sB4[kc2 * 512 + (wc * 4 + nb) * 32 + lane];
            // k8-lo across all tiles
#pragma unroll
            for (int mt = 0; mt < 4; mt++)
#pragma unroll
                for (int nt = 0; nt < 4; nt++)
                    mma_tf32(acc[mt][nt],
                             af[2 * mt].x, af[2 * mt + 1].x,
                             af[2 * mt].y, af[2 * mt + 1].y,
                             bf[nt].x, bf[nt].y);
            // k8-hi across all tiles
#pragma unroll
            for (int mt = 0; mt < 4; mt++)
#pragma unroll
                for (int nt = 0; nt < 4; nt++)
                    mma_tf32(acc[mt][nt],
                             af[2 * mt].z, af[2 * mt + 1].z,
                             af[2 * mt].w, af[2 * mt + 1].w,
                             bf[nt].z, bf[nt].w);
        }
        __syncthreads();
    }

    // Fused LSTM epilogue (unchanged mapping).
    const int b8 = (tile & 15) * 4 + wc;
    float* hn = (float*)g_hf4[cur ^ 1];
    const int jb = b8 * 8 + 2 * tig;
    const float2 bi = *(const float2*)&g_bc[jb];
    const float2 bfv = *(const float2*)&g_bc[512 + jb];
    const float2 bg = *(const float2*)&g_bc[1024 + jb];
    const float2 bo = *(const float2*)&g_bc[1536 + jb];
#pragma unroll
    for (int mt = 0; mt < 4; mt++) {
#pragma unroll
        for (int rh = 0; rh < 2; rh++) {
            const int m = (tile >> 4) * 128 + wr * 64 + mt * 16 + rh * 8 + gid;
            float2 cv = *(const float2*)&g_c[(size_t)m * HID + jb];
            float hh[2];
#pragma unroll
            for (int c = 0; c < 2; c++) {
                const int r = rh * 2 + c;
                float gi = acc[mt][0][r] + (c ? bi.y : bi.x);
                float gf = acc[mt][1][r] + (c ? bfv.y : bfv.x);
                float gg = acc[mt][2][r] + (c ? bg.y : bg.x);
                float go = acc[mt][3][r] + (c ? bo.y : bo.x);
                float cn = fast_sig(gf) * (c ? cv.y : cv.x)
                         + fast_sig(gi) * fast_tanh(gg);
                if (c) cv.y = cn; else cv.x = cn;
                hh[c] = tfr(fast_sig(go) * fast_tanh(cn));
            }
            *(float2*)&g_c[(size_t)m * HID + jb] = cv;
#pragma unroll
            for (int c = 0; c < 2; c++) {
                int j = jb + c;
                int kc = j >> 4, rem = j & 15, s = rem >> 2, tg2 = rem & 3;
                hn[(((kc * 128 + (m >> 3)) * 32 + gid * 4 + tg2) << 2) + s] = hh[c];
            }
        }
    }
}

// ---------------------------------------------------------------------------
// Scatter one activation value into B-frag layout: [kc][b*4+tg][s]
// ---------------------------------------------------------------------------
__device__ __forceinline__ void store_zf(float* sZ, int b, int f, float v) {
    int kc = f >> 4, rem = f & 15, s = rem >> 2, tg = rem & 3;
    sZ[((kc * 32 + b * 4 + tg) << 2) + s] = v;
}

// ---------------------------------------------------------------------------
// Fused 3-layer MLP, TRANSPOSED: W is the m-operand (full m16 tiles),
// the CTA's 8 batch rows are the n8 operand. 4-way acc split per warp.
// ---------------------------------------------------------------------------
__device__ void mlp_phase(int t, const float4* __restrict__ hf,
                          const float* __restrict__ b1,
                          const float* __restrict__ b2,
                          const float* __restrict__ b3,
                          float* __restrict__ out, float* dsm) {
    const int bid = blockIdx.x;
    const int tid = threadIdx.x, lane = tid & 31, w = tid >> 5;
    const int gid = lane >> 2, tig = lane & 3;
    float4* sH = (float4*)(dsm + 24576);   // 16KB: h B-frags [kc 0..31][lane]
    float* sZ1 = dsm + 24576 + 4096;       // 4KB
    float* sZ2 = sZ1 + 1024;               // 4KB

    // stage this CTA's 8 h rows
#pragma unroll
    for (int j = 0; j < 4; j++) {
        int u = j * 256 + tid;
        unsigned dst = (unsigned)__cvta_generic_to_shared(sH + u);
        const float4* src = hf + (((size_t)(u >> 5) * 128 + bid) << 5) + (u & 31);
        CP_ASYNC16(dst, src);
    }
    CP_COMMIT();
    asm volatile("cp.async.wait_group 0;\n" ::: "memory");
    __syncthreads();

    // ---- z1^T = W1 (m) x h (n): warp w -> m16 tile w ----
    {
        float acc[4][4];
#pragma unroll
        for (int i = 0; i < 4; i++)
#pragma unroll
            for (int r = 0; r < 4; r++) acc[i][r] = 0.f;
        const float4* w1p = g_W1A + (size_t)w * 2048;   // 32 kc * 32 lane * 2
#pragma unroll 4
        for (int kc = 0; kc < 32; kc++) {
            float4 bv = sH[kc * 32 + lane];
            float4 alo = w1p[(kc * 32 + lane) * 2];
            float4 ahi = w1p[(kc * 32 + lane) * 2 + 1];
            mma_tf32(acc[(2 * kc) & 3], alo.x, alo.y, alo.z, alo.w, bv.x, bv.y);
            mma_tf32(acc[(2 * kc + 1) & 3], ahi.x, ahi.y, ahi.z, ahi.w, bv.z, bv.w);
        }
        float c0 = acc[0][0] + acc[1][0] + acc[2][0] + acc[3][0];
        float c1 = acc[0][1] + acc[1][1] + acc[2][1] + acc[3][1];
        float c2 = acc[0][2] + acc[1][2] + acc[2][2] + acc[3][2];
        float c3 = acc[0][3] + acc[1][3] + acc[2][3] + acc[3][3];
        int f0 = w * 16 + gid;
        float bb0 = b1[f0], bb8 = b1[f0 + 8];
        store_zf(sZ1, 2 * tig,     f0,     tfr(fmaxf(c0 + bb0, 0.f)));
        store_zf(sZ1, 2 * tig + 1, f0,     tfr(fmaxf(c1 + bb0, 0.f)));
        store_zf(sZ1, 2 * tig,     f0 + 8, tfr(fmaxf(c2 + bb8, 0.f)));
        store_zf(sZ1, 2 * tig + 1, f0 + 8, tfr(fmaxf(c3 + bb8, 0.f)));
    }
    __syncthreads();

    // ---- z2^T = W2 x z1: warp w -> m16 tile w ----
    {
        float acc[4][4];
#pragma unroll
        for (int i = 0; i < 4; i++)
#pragma unroll
            for (int r = 0; r < 4; r++) acc[i][r] = 0.f;
        const float4* w2p = g_W2A + (size_t)w * 512;    // 8 kc * 32 lane * 2
        const float4* sz1 = (const float4*)sZ1;
#pragma unroll
        for (int kc = 0; kc < 8; kc++) {
            float4 bv = sz1[kc * 32 + lane];
            float4 alo = w2p[(kc * 32 + lane) * 2];
            float4 ahi = w2p[(kc * 32 + lane) * 2 + 1];
            mma_tf32(acc[(2 * kc) & 3], alo.x, alo.y, alo.z, alo.w, bv.x, bv.y);
            mma_tf32(acc[(2 * kc + 1) & 3], ahi.x, ahi.y, ahi.z, ahi.w, bv.z, bv.w);
        }
        float c0 = acc[0][0] + acc[1][0] + acc[2][0] + acc[3][0];
        float c1 = acc[0][1] + acc[1][1] + acc[2][1] + acc[3][1];
        float c2 = acc[0][2] + acc[1][2] + acc[2][2] + acc[3][2];
        float c3 = acc[0][3] + acc[1][3] + acc[2][3] + acc[3][3];
        int f0 = w * 16 + gid;
        float bb0 = b2[f0], bb8 = b2[f0 + 8];
        store_zf(sZ2, 2 * tig,     f0,     tfr(fmaxf(c0 + bb0, 0.f)));
        store_zf(sZ2, 2 * tig + 1, f0,     tfr(fmaxf(c1 + bb0, 0.f)));
        store_zf(sZ2, 2 * tig,     f0 + 8, tfr(fmaxf(c2 + bb8, 0.f)));
        store_zf(sZ2, 2 * tig + 1, f0 + 8, tfr(fmaxf(c3 + bb8, 0.f)));
    }
    __syncthreads();

    // ---- tok^T = W3 x z2: warp w -> m16 tiles {w, w+8} ----
    {
        float acc[4][4];
#pragma unroll
        for (int i = 0; i < 4; i++)
#pragma unroll
            for (int r = 0; r < 4; r++) acc[i][r] = 0.f;
        const float4* w3a = g_W3A + (size_t)w * 512;
        const float4* w3b = g_W3A + (size_t)(w + 8) * 512;
        const float4* sz2 = (const float4*)sZ2;
#pragma unroll
        for (int kc = 0; kc < 8; kc++) {
            float4 bv = sz2[kc * 32 + lane];
            float4 alo = w3a[(kc * 32 + lane) * 2];
            float4 ahi = w3a[(kc * 32 + lane) * 2 + 1];
            float4 clo = w3b[(kc * 32 + lane) * 2];
            float4 chi = w3b[(kc * 32 + lane) * 2 + 1];
            mma_tf32(acc[0], alo.x, alo.y, alo.z, alo.w, bv.x, bv.y);
            mma_tf32(acc[1], ahi.x, ahi.y, ahi.z, ahi.w, bv.z, bv.w);
            mma_tf32(acc[2], clo.x, clo.y, clo.z, clo.w, bv.x, bv.y);
            mma_tf32(acc[3], chi.x, chi.y, chi.z, chi.w, bv.z, bv.w);
        }
        float* obase = out + (size_t)(t + 1) * EMB;
        const size_t rstr = (size_t)SEQL * EMB;
        const int r0 = bid * 8 + 2 * tig, r1 = r0 + 1;
#pragma unroll
        for (int ti = 0; ti < 2; ti++) {
            int f0 = (w + 8 * ti) * 16 + gid;
            float c0 = acc[2 * ti][0] + acc[2 * ti + 1][0];
            float c1 = acc[2 * ti][1] + acc[2 * ti + 1][1];
            float c2 = acc[2 * ti][2] + acc[2 * ti + 1][2];
            float c3 = acc[2 * ti][3] + acc[2 * ti + 1][3];
            float bb0 = b3[f0], bb8 = b3[f0 + 8];
            obase[(size_t)r0 * rstr + f0]     = c0 + bb0;
            obase[(size_t)r1 * rstr + f0]     = c1 + bb0;
            obase[(size_t)r0 * rstr + f0 + 8] = c2 + bb8;
            obase[(size_t)r1 * rstr + f0 + 8] = c3 + bb8;
        }
    }
}

// ---------------------------------------------------------------------------
// Persistent kernel: ONE grid sync per step.
// ---------------------------------------------------------------------------
__global__ void __launch_bounds__(NTHR, 1)
lstm_kernel(const float* __restrict__ b1, const float* __restrict__ b2,
            const float* __restrict__ b3, float* __restrict__ out) {
    extern __shared__ __align__(16) float dsm[];
    int cur = 0;
    for (int t = 0; t < STEPS; t++) {
        phase_gates(t, cur, dsm);
        grid_sync();
        mlp_phase(t, g_hf4[cur ^ 1], b1, b2, b3, out, dsm);
        cur ^= 1;
    }
}

// ---------------------------------------------------------------------------
extern "C" void kernel_launch(void* const* d_in, const int* in_sizes, int n_in,
                              void* d_out, int out_size) {
    (void)in_sizes; (void)n_in; (void)out_size;
    const float* hidden = (const float*)d_in[0];
    const float* pts    = (const float*)d_in[1];
    const float* W_ih   = (const float*)d_in[2];
    const float* W_hh   = (const float*)d_in[3];
    const float* b_ih   = (const float*)d_in[4];
    const float* b_hh   = (const float*)d_in[5];
    const float* W1     = (const float*)d_in[6];
    const float* b1     = (const float*)d_in[7];
    const float* W2     = (const float*)d_in[8];
    const float* b2     = (const float*)d_in[9];
    const float* W3     = (const float*)d_in[10];
    const float* b3     = (const float*)d_in[11];
    float* out = (float*)d_out;

    cudaFuncSetAttribute(lstm_kernel, cudaFuncAttributeMaxDynamicSharedMemorySize, DSMEM);
    init_kernel<<<4096, 256>>>(hidden, pts, W_ih, W_hh, b_ih, b_hh, W1, W2, W3, out);
    lstm_kernel<<<NBLK, NTHR, DSMEM>>>(b1, b2, b3, out);
}